// round 1
// baseline (speedup 1.0000x reference)
#include <cuda_runtime.h>
#include <math.h>

// Problem constants
#define BATCH 16
#define NAK   3      // anchors per scale
#define NC    80     // classes
#define NT    300    // targets
#define NENT_PER_SCALE (5 * NAK * NT)   // 4500
#define NENT_TOTAL     (3 * NENT_PER_SCALE) // 13500

// tobj cell counts: 16*3*80*80=307200, 16*3*40*40=76800, 16*3*20*20=19200
#define CELLS0 307200
#define CELLS1 76800
#define CELLS2 19200
#define CELLS_TOTAL (CELLS0 + CELLS1 + CELLS2) // 403200

// Scratch (statically allocated; re-initialized every launch for graph replay determinism)
__device__ double g_lbox[3];
__device__ double g_lcls[3];
__device__ double g_lobj[3];
__device__ int    g_nv[3];
__device__ float  g_tobj[CELLS_TOTAL];

__device__ __forceinline__ float bce_logits(float x, float t) {
    return fmaxf(x, 0.0f) - x * t + log1pf(expf(-fabsf(x)));
}

// ---------------------------------------------------------------------------
// Kernel 1: zero scratch
// ---------------------------------------------------------------------------
__global__ void k_init() {
    int i = blockIdx.x * blockDim.x + threadIdx.x;
    for (; i < CELLS_TOTAL; i += gridDim.x * blockDim.x) g_tobj[i] = 0.0f;
    if (blockIdx.x == 0 && threadIdx.x < 3) {
        g_lbox[threadIdx.x] = 0.0;
        g_lcls[threadIdx.x] = 0.0;
        g_lobj[threadIdx.x] = 0.0;
        g_nv[threadIdx.x]   = 0;
    }
}

// ---------------------------------------------------------------------------
// Kernel 2: one warp per (scale, offset, anchor, target) entry.
// Computes validity masks; for valid entries gathers the 85-channel prediction
// vector, computes CIoU (lbox), class BCE (lcls), and scatter-max into tobj.
// ---------------------------------------------------------------------------
__global__ void k_entry(const float* __restrict__ p0,
                        const float* __restrict__ p1,
                        const float* __restrict__ p2,
                        const float* __restrict__ tg,
                        const float* __restrict__ anchors) {
    int g    = (blockIdx.x * blockDim.x + threadIdx.x) >> 5;
    int lane = threadIdx.x & 31;
    if (g >= NENT_TOTAL) return;

    int scale = g / NENT_PER_SCALE;
    int e     = g % NENT_PER_SCALE;
    int o     = e / (NAK * NT);         // offset index 0..4
    int a     = (e % (NAK * NT)) / NT;  // anchor 0..2
    int t     = e % NT;                 // target 0..299

    int   W = (scale == 0) ? 80 : (scale == 1) ? 40 : 20;
    int   H = W;
    float stride = 640.0f / (float)W;
    const float* pred = (scale == 0) ? p0 : (scale == 1) ? p1 : p2;

    // target row: [b, cls, x, y, w, h] (normalized)
    float tbf = tg[t * 6 + 0];
    int   cls = (int)tg[t * 6 + 1];
    float gx  = tg[t * 6 + 2] * (float)W;
    float gy  = tg[t * 6 + 3] * (float)H;
    float gw  = tg[t * 6 + 4] * (float)W;
    float gh  = tg[t * 6 + 5] * (float)H;

    float ax = anchors[(scale * 3 + a) * 2 + 0] / stride;
    float ay = anchors[(scale * 3 + a) * 2 + 1] / stride;

    // anchor ratio mask
    float rx = gw / ax, ry = gh / ay;
    float rmax = fmaxf(fmaxf(rx, 1.0f / rx), fmaxf(ry, 1.0f / ry));
    bool amask = rmax < 4.0f;

    // offset-selection mask
    bool  sel;
    float offx = 0.0f, offy = 0.0f;
    switch (o) {
        case 0: sel = true; break;
        case 1: sel = (fmodf(gx, 1.0f) < 0.5f) && (gx > 1.0f); offx = 1.0f;  break;
        case 2: sel = (fmodf(gy, 1.0f) < 0.5f) && (gy > 1.0f); offy = 1.0f;  break;
        case 3: { float xi = (float)W - gx;
                  sel = (fmodf(xi, 1.0f) < 0.5f) && (xi > 1.0f); offx = -1.0f; } break;
        default:{ float yi = (float)H - gy;
                  sel = (fmodf(yi, 1.0f) < 0.5f) && (yi > 1.0f); offy = -1.0f; } break;
    }
    if (!(sel && amask)) return;   // uniform across warp

    int b    = (int)tbf;
    int gijx = (int)(gx - offx);   // trunc-toward-zero, matches astype(int32)
    int gijy = (int)(gy - offy);
    int gi = min(max(gijx, 0), W - 1);
    int gj = min(max(gijy, 0), H - 1);

    int HW = H * W;
    const float* base = pred + (size_t)(b * 255 + a * 85) * HW + (size_t)gj * W + gi;

    // class BCE: lanes cover channels 5..84
    float csum = 0.0f;
    for (int ch = 5 + lane; ch < 85; ch += 32) {
        float x  = base[(size_t)ch * HW];
        float tt = ((ch - 5) == cls) ? 1.0f : 0.0f;
        csum += bce_logits(x, tt);
    }
    #pragma unroll
    for (int m = 16; m; m >>= 1) csum += __shfl_xor_sync(0xffffffffu, csum, m);

    if (lane == 0) {
        float s0 = base[0];
        float s1 = base[(size_t)1 * HW];
        float s2 = base[(size_t)2 * HW];
        float s3 = base[(size_t)3 * HW];

        float px = 1.0f / (1.0f + expf(-s0));
        float py = 1.0f / (1.0f + expf(-s1));
        float pw = expf(s2) * ax;
        float ph = expf(s3) * ay;
        float tbx = gx - (float)gijx;
        float tby = gy - (float)gijy;

        // CIoU (match reference formulas)
        float b1x1 = px - pw * 0.5f, b1x2 = px + pw * 0.5f;
        float b1y1 = py - ph * 0.5f, b1y2 = py + ph * 0.5f;
        float b2x1 = tbx - gw * 0.5f, b2x2 = tbx + gw * 0.5f;
        float b2y1 = tby - gh * 0.5f, b2y2 = tby + gh * 0.5f;

        float iw = fmaxf(fminf(b1x2, b2x2) - fmaxf(b1x1, b2x1), 0.0f);
        float ih = fmaxf(fminf(b1y2, b2y2) - fmaxf(b1y1, b2y1), 0.0f);
        float inter = iw * ih;
        float w1 = b1x2 - b1x1, h1 = b1y2 - b1y1;
        float w2 = b2x2 - b2x1, h2 = b2y2 - b2y1;
        float uni = w1 * h1 + w2 * h2 - inter + 1e-16f;
        float iou = inter / uni;
        float cw  = fmaxf(b1x2, b2x2) - fminf(b1x1, b2x1);
        float chh = fmaxf(b1y2, b2y2) - fminf(b1y1, b2y1);
        float c2  = cw * cw + chh * chh + 1e-16f;
        float dx  = b2x1 + b2x2 - b1x1 - b1x2;
        float dy  = b2y1 + b2y2 - b1y1 - b1y2;
        float rho2 = (dx * dx + dy * dy) * 0.25f;
        float da = atanf(w2 / h2) - atanf(w1 / h1);
        float v  = (4.0f / (3.14159f * 3.14159f)) * da * da;
        float alpha = v / (v - iou + 1.0f);
        float ciou  = iou - (rho2 / c2 + v * alpha);

        atomicAdd(&g_lbox[scale], (double)(1.0f - ciou));
        atomicAdd(&g_nv[scale], 1);
        atomicAdd(&g_lcls[scale], (double)csum);

        float iou_d = fmaxf(ciou, 0.0f);
        int sbase = (scale == 0) ? 0 : (scale == 1) ? CELLS0 : (CELLS0 + CELLS1);
        int idx = sbase + ((b * 3 + a) * H + gj) * W + gi;
        // nonnegative floats compare identically as ints
        atomicMax((int*)&g_tobj[idx], __float_as_int(iou_d));
    }
}

// ---------------------------------------------------------------------------
// Kernel 3: objectness BCE over all cells, block-reduced.
// Block size 256 divides all scale boundaries -> each block is single-scale.
// ---------------------------------------------------------------------------
__global__ void k_obj(const float* __restrict__ p0,
                      const float* __restrict__ p1,
                      const float* __restrict__ p2) {
    int i = blockIdx.x * blockDim.x + threadIdx.x;  // < CELLS_TOTAL exactly

    int scale, W, base;
    const float* pred;
    if (i < CELLS0)               { scale = 0; W = 80; base = 0;               pred = p0; }
    else if (i < CELLS0 + CELLS1) { scale = 1; W = 40; base = CELLS0;          pred = p1; }
    else                          { scale = 2; W = 20; base = CELLS0 + CELLS1; pred = p2; }

    int idx  = i - base;
    int HW   = W * W;
    int wpos = idx % HW;          // j*W + w
    int rest = idx / HW;          // b*3 + a
    int a = rest % 3, b = rest / 3;

    float x = pred[(size_t)(b * 255 + a * 85 + 4) * HW + wpos];
    float t = g_tobj[i];
    float val = bce_logits(x, t);

    // warp reduce
    #pragma unroll
    for (int m = 16; m; m >>= 1) val += __shfl_xor_sync(0xffffffffu, val, m);

    __shared__ float warpsum[8];
    int lane = threadIdx.x & 31, wid = threadIdx.x >> 5;
    if (lane == 0) warpsum[wid] = val;
    __syncthreads();
    if (wid == 0) {
        float s = (lane < 8) ? warpsum[lane] : 0.0f;
        #pragma unroll
        for (int m = 4; m; m >>= 1) s += __shfl_xor_sync(0xffffffffu, s, m);
        if (lane == 0) atomicAdd(&g_lobj[scale], (double)s);
    }
}

// ---------------------------------------------------------------------------
// Kernel 4: finalize 4 scalars
// ---------------------------------------------------------------------------
__global__ void k_fin(float* out, int out_size) {
    const double cells[3] = {(double)CELLS0, (double)CELLS1, (double)CELLS2};
    double lbox = 0.0, lobj = 0.0, lcls = 0.0;
    for (int s = 0; s < 3; s++) {
        double nv = (double)g_nv[s];
        lbox += g_lbox[s] / fmax(nv, 1.0);
        lcls += g_lcls[s] / fmax(nv * 80.0, 1.0);
        lobj += g_lobj[s] / cells[s];
    }
    lbox *= 0.05;
    lcls *= 0.5;
    double loss = lbox + lobj + lcls;
    out[0] = (float)loss;
    if (out_size >= 4) {
        out[1] = (float)lbox;
        out[2] = (float)lobj;
        out[3] = (float)lcls;
    }
}

extern "C" void kernel_launch(void* const* d_in, const int* in_sizes, int n_in,
                              void* d_out, int out_size) {
    const float* p0      = (const float*)d_in[0];
    const float* p1      = (const float*)d_in[1];
    const float* p2      = (const float*)d_in[2];
    const float* targets = (const float*)d_in[3];
    const float* anchors = (const float*)d_in[4];
    float* out = (float*)d_out;

    k_init<<<CELLS_TOTAL / 256, 256>>>();
    k_entry<<<(NENT_TOTAL * 32 + 255) / 256, 256>>>(p0, p1, p2, targets, anchors);
    k_obj<<<CELLS_TOTAL / 256, 256>>>(p0, p1, p2);
    k_fin<<<1, 1>>>(out, out_size);
}